// round 5
// baseline (speedup 1.0000x reference)
#include <cuda_runtime.h>

#define NMAX 100000
#define EMAX 1600000
#define NG 64
#define NH 64

// ---- scratch (static device globals; no allocations allowed) ----
__device__ __align__(16) float g_h[(size_t)NMAX * NH];
__device__ __align__(16) float g_agg[(size_t)NMAX * NH];
__device__ __align__(16) float g_out[(size_t)NMAX * NH];
__device__ float g_deg[NMAX];
__device__ float g_dinv[NMAX];
__device__ int   g_src[EMAX];
__device__ int   g_dst[EMAX];
__device__ float g_norm[EMAX];
__device__ float g_pooled[NG * NH];

// ---------------- degree / norm prep ----------------

__global__ void k_init_deg(int n) {
    int i = blockIdx.x * blockDim.x + threadIdx.x;
    if (i < n) g_deg[i] = 1.0f;   // self-loop contributes 1 to every degree
}

__global__ void k_prep_edges(const int* __restrict__ ei, int E, int n) {
    int e = blockIdx.x * blockDim.x + threadIdx.x;
    if (e < E) {
        int s = ei[e];
        int d = ei[(size_t)E + e];
        // clamp: identity on valid data, crash-proof otherwise
        s = s < 0 ? 0 : (s >= n ? n - 1 : s);
        d = d < 0 ? 0 : (d >= n ? n - 1 : d);
        g_src[e] = s;
        g_dst[e] = d;
        atomicAdd(&g_deg[d], 1.0f);
    }
}

__global__ void k_dinv(int n) {
    int i = blockIdx.x * blockDim.x + threadIdx.x;
    if (i < n) g_dinv[i] = rsqrtf(g_deg[i]);   // deg >= 1 always (self-loop)
}

__global__ void k_norm(int E) {
    int e = blockIdx.x * blockDim.x + threadIdx.x;
    if (e < E) g_norm[e] = g_dinv[g_src[e]] * g_dinv[g_dst[e]];
}

// ---------------- GEMM: H[n,64] = X[n,K] @ W[K,64] ----------------
// 64-row x 64-col tile per 256-thread block; W + X tile staged in smem in
// K-chunks of 64. Each thread owns a 4x4 microtile.

template<int K, bool USE_GOUT>
__global__ void __launch_bounds__(256) k_gemm(const float* __restrict__ Xin,
                                              const float* __restrict__ W, int n) {
    __shared__ float Ws[64 * 64];    // 16 KB
    __shared__ float Xs[64 * 68];    // 17.4 KB (stride 68 kills bank conflicts)

    const float* __restrict__ X = USE_GOUT ? (const float*)g_out : Xin;
    const int tid  = threadIdx.x;
    const int row0 = blockIdx.x * 64;
    const int r = (tid >> 4) << 2;   // 0..60
    const int c = (tid & 15) << 2;   // 0..60

    float acc[4][4] = {};

    for (int kc = 0; kc < K; kc += 64) {
        // W rows kc..kc+63 are contiguous: 64*64 floats
        for (int i = tid; i < 64 * 16; i += 256)
            ((float4*)Ws)[i] = ((const float4*)(W + (size_t)kc * 64))[i];
        // X tile: 64 rows x 64 cols
        for (int i = tid; i < 64 * 16; i += 256) {
            int rr = i >> 4, c4 = i & 15;
            float4 v = make_float4(0.f, 0.f, 0.f, 0.f);
            if (row0 + rr < n)
                v = *((const float4*)(X + (size_t)(row0 + rr) * K + kc + c4 * 4));
            *((float4*)(Xs + rr * 68 + c4 * 4)) = v;
        }
        __syncthreads();

        #pragma unroll 16
        for (int k = 0; k < 64; k++) {
            float4 wb = *((const float4*)(Ws + k * 64 + c));
            float a0 = Xs[(r + 0) * 68 + k];
            float a1 = Xs[(r + 1) * 68 + k];
            float a2 = Xs[(r + 2) * 68 + k];
            float a3 = Xs[(r + 3) * 68 + k];
            acc[0][0] += a0 * wb.x; acc[0][1] += a0 * wb.y; acc[0][2] += a0 * wb.z; acc[0][3] += a0 * wb.w;
            acc[1][0] += a1 * wb.x; acc[1][1] += a1 * wb.y; acc[1][2] += a1 * wb.z; acc[1][3] += a1 * wb.w;
            acc[2][0] += a2 * wb.x; acc[2][1] += a2 * wb.y; acc[2][2] += a2 * wb.z; acc[2][3] += a2 * wb.w;
            acc[3][0] += a3 * wb.x; acc[3][1] += a3 * wb.y; acc[3][2] += a3 * wb.z; acc[3][3] += a3 * wb.w;
        }
        __syncthreads();
    }

    #pragma unroll
    for (int i = 0; i < 4; i++) {
        int rr = row0 + r + i;
        if (rr < n)
            *((float4*)(g_h + (size_t)rr * 64 + c)) =
                make_float4(acc[i][0], acc[i][1], acc[i][2], acc[i][3]);
    }
}

// ---------------- zero agg ----------------

__global__ void k_zero(int n4) {
    int i = blockIdx.x * blockDim.x + threadIdx.x;
    if (i < n4) ((float4*)g_agg)[i] = make_float4(0.f, 0.f, 0.f, 0.f);
}

// ---------------- edge scatter: agg[dst] += h[src]*norm ----------------
// 16 lanes per edge, one float4 per lane, vector red.global (16B atomics).

__global__ void __launch_bounds__(256) k_scatter(int E) {
    int gid = blockIdx.x * blockDim.x + threadIdx.x;
    int e = gid >> 4;
    if (e >= E) return;
    int l = gid & 15;
    int s = g_src[e];
    int d = g_dst[e];
    float nrm = g_norm[e];
    float4 v = *((const float4*)(g_h + (size_t)s * 64 + l * 4));
    float* p = g_agg + (size_t)d * 64 + l * 4;
    asm volatile("red.global.add.v4.f32 [%0], {%1, %2, %3, %4};"
                 :: "l"(p), "f"(v.x * nrm), "f"(v.y * nrm), "f"(v.z * nrm), "f"(v.w * nrm)
                 : "memory");
}

// ---------------- epilogue: out = relu(agg + h*dinv^2 + b) ----------------
// (self-loop term h[i]*dinv[i]^2 folded in analytically)

__global__ void k_finalize(const float* __restrict__ bias, int n) {
    int idx = blockIdx.x * blockDim.x + threadIdx.x;
    if (idx >= n * 16) return;
    int node = idx >> 4, l = idx & 15;
    float di = g_dinv[node];
    float d2 = di * di;
    float4 h4 = ((const float4*)g_h)[idx];
    float4 a4 = ((const float4*)g_agg)[idx];
    // scalar bias reads (no alignment assumption on harness pointer)
    float b0 = bias[l * 4 + 0], b1 = bias[l * 4 + 1];
    float b2 = bias[l * 4 + 2], b3 = bias[l * 4 + 3];
    float4 o;
    o.x = fmaxf(fmaf(h4.x, d2, a4.x) + b0, 0.f);
    o.y = fmaxf(fmaf(h4.y, d2, a4.y) + b1, 0.f);
    o.z = fmaxf(fmaf(h4.z, d2, a4.z) + b2, 0.f);
    o.w = fmaxf(fmaf(h4.w, d2, a4.w) + b3, 0.f);
    ((float4*)g_out)[idx] = o;
}

// ---------------- mean-pool per graph (batch is sorted -> binary search) ----------------

__device__ __forceinline__ int lower_bound_i(const int* b, int n, int v) {
    int lo = 0, hi = n;
    while (lo < hi) {
        int m = (lo + hi) >> 1;
        if (b[m] < v) lo = m + 1; else hi = m;
    }
    return lo;
}

__global__ void k_pool(const int* __restrict__ batch, int n) {
    __shared__ int s_bounds[2];
    __shared__ float red[256];
    int g = blockIdx.x;
    if (threadIdx.x == 0) {
        s_bounds[0] = lower_bound_i(batch, n, g);
        s_bounds[1] = lower_bound_i(batch, n, g + 1);
    }
    __syncthreads();
    int start = s_bounds[0], end = s_bounds[1];
    int f = threadIdx.x & 63, j = threadIdx.x >> 6;  // 4 partial sums per feature
    float acc = 0.f;
    for (int node = start + j; node < end; node += 4)
        acc += g_out[(size_t)node * 64 + f];
    red[threadIdx.x] = acc;
    __syncthreads();
    if (j == 0) {
        float s = red[f] + red[64 + f] + red[128 + f] + red[192 + f];
        float cnt = (float)(end - start);
        g_pooled[g * 64 + f] = s / fmaxf(cnt, 1.0f);
    }
}

// ---------------- final linear + softmax ----------------

__global__ void k_final(const float* __restrict__ Wl, const float* __restrict__ bl,
                        float* __restrict__ out) {
    int g = threadIdx.x;
    if (g >= NG) return;
    float p[64];
    #pragma unroll
    for (int f = 0; f < 64; f++) p[f] = g_pooled[g * 64 + f];
    float logits[10];
    #pragma unroll
    for (int c = 0; c < 10; c++) {
        float s = bl[c];
        #pragma unroll
        for (int f = 0; f < 64; f++) s += p[f] * Wl[f * 10 + c];
        logits[c] = s;
    }
    float m = logits[0];
    #pragma unroll
    for (int c = 1; c < 10; c++) m = fmaxf(m, logits[c]);
    float sum = 0.f;
    #pragma unroll
    for (int c = 0; c < 10; c++) { logits[c] = expf(logits[c] - m); sum += logits[c]; }
    float inv = 1.0f / sum;
    #pragma unroll
    for (int c = 0; c < 10; c++) out[g * 10 + c] = logits[c] * inv;
}

// ---------------- launch ----------------
// Inputs bound BY ELEMENT COUNT (robust to metadata ordering). NOTE: JAX with
// default x64-disabled config downcasts int64 -> int32, so edge_index and
// batch are int32 buffers (metadata: int32 -> const int*).

extern "C" void kernel_launch(void* const* d_in, const int* in_sizes, int n_in,
                              void* d_out, int out_size) {
    (void)out_size;
    const float* x = nullptr;
    const int* ei = nullptr;
    const int* batch = nullptr;
    const float *W1 = nullptr, *W2 = nullptr, *W3 = nullptr, *Wl = nullptr;
    const float *b1 = nullptr, *b2 = nullptr, *b3 = nullptr, *bl = nullptr;
    int ei_elems = 0, batch_elems = 0;
    int n4096 = 0, n64 = 0;

    for (int i = 0; i < n_in; i++) {
        int sz = in_sizes[i];
        const void* p = d_in[i];
        if (sz == 100000 * 128)      x = (const float*)p;
        else if (sz == 2 * 1600000)  { ei = (const int*)p; ei_elems = sz; }
        else if (sz == 100000)       { batch = (const int*)p; batch_elems = sz; }
        else if (sz == 128 * 64)     W1 = (const float*)p;
        else if (sz == 64 * 64)      { if (n4096++ == 0) W2 = (const float*)p; else W3 = (const float*)p; }
        else if (sz == 64)           { if (n64 == 0) b1 = (const float*)p;
                                       else if (n64 == 1) b2 = (const float*)p;
                                       else b3 = (const float*)p; n64++; }
        else if (sz == 64 * 10)      Wl = (const float*)p;
        else if (sz == 10)           bl = (const float*)p;
    }
    if (!x || !ei || !batch || !W1 || !W2 || !W3 || !b1 || !b2 || !b3 || !Wl || !bl)
        return;

    int n = batch_elems;     if (n > NMAX) n = NMAX;
    int E = ei_elems / 2;    if (E > EMAX) E = EMAX;

    const int TB = 256;
    const int nbN  = (n + TB - 1) / TB;
    const int nbE  = (E + TB - 1) / TB;
    const int nbF4 = (n * 16 + TB - 1) / TB;            // n*16 float4s of a [n,64] buffer
    const int nbSc = (int)(((size_t)E * 16 + TB - 1) / TB);
    const int nbGm = (n + 63) / 64;

    // prep: degree (with self-loop), dinv, per-edge norm
    k_init_deg<<<nbN, TB>>>(n);
    k_prep_edges<<<nbE, TB>>>(ei, E, n);
    k_dinv<<<nbN, TB>>>(n);
    k_norm<<<nbE, TB>>>(E);

    // layer 1 (K=128, input = x)
    k_gemm<128, false><<<nbGm, TB>>>(x, W1, n);
    k_zero<<<nbF4, TB>>>(n * 16);
    k_scatter<<<nbSc, TB>>>(E);
    k_finalize<<<nbF4, TB>>>(b1, n);

    // layer 2 (K=64, input = g_out)
    k_gemm<64, true><<<nbGm, TB>>>(nullptr, W2, n);
    k_zero<<<nbF4, TB>>>(n * 16);
    k_scatter<<<nbSc, TB>>>(E);
    k_finalize<<<nbF4, TB>>>(b2, n);

    // layer 3
    k_gemm<64, true><<<nbGm, TB>>>(nullptr, W3, n);
    k_zero<<<nbF4, TB>>>(n * 16);
    k_scatter<<<nbSc, TB>>>(E);
    k_finalize<<<nbF4, TB>>>(b3, n);

    // pool + classify
    k_pool<<<NG, TB>>>(batch, n);
    k_final<<<1, 64>>>(Wl, bl, (float*)d_out);
}